// round 8
// baseline (speedup 1.0000x reference)
#include <cuda_runtime.h>
#include <math.h>

// Problem constants
#define BB   2
#define SS   2048
#define DD   1024
#define HH   16
#define DK   64
#define MROWS (BB * SS)      // 4096
#define SCALE 0.125f         // 1/sqrt(64)

// ---------------------------------------------------------------------------
// Scratch (allocation-free rule: __device__ globals)
// ---------------------------------------------------------------------------
__device__ float g_Q[MROWS * DD];
__device__ float g_K[MROWS * DD];
__device__ float g_V[MROWS * DD];
__device__ float g_AO[MROWS * DD];

// ---------------------------------------------------------------------------
// SGEMM core: C[M,N] = A[M,K] @ W[K,N], row-major, M%128==0, N%128==0, K%8==0.
// 128x128 tile, BK=8, 256 threads, 8x8 register microtile per thread.
// 2-stage smem double buffering: one __syncthreads per K-step, global
// prefetch of tile k+1 overlapped with compute on tile k.
// ---------------------------------------------------------------------------
__device__ __forceinline__ void sgemm_body(
    const float* __restrict__ A, const float* __restrict__ W,
    float* __restrict__ C, int M, int N, int K,
    float (*As)[8][128], float (*Bs)[8][128])
{
    const int tid = threadIdx.x;
    const int bm  = blockIdx.y * 128;
    const int bn  = blockIdx.x * 128;
    const int ty  = tid >> 4;           // 0..15 row group
    const int tx  = tid & 15;           // 0..15 col group

    const int arow = tid >> 1;          // 0..127
    const int acol = (tid & 1) << 2;    // 0 or 4
    const int brow = tid >> 5;          // 0..7
    const int bcol = (tid & 31) << 2;   // 0..124

    const float* Ap = A + (size_t)(bm + arow) * K + acol;
    const float* Wp = W + (size_t)brow * N + bn + bcol;

    float acc[8][8] = {};

    // Prologue: load tile 0 into stage 0
    float4 av = *(const float4*)(Ap);
    float4 wv = *(const float4*)(Wp);
    As[0][acol + 0][arow] = av.x;
    As[0][acol + 1][arow] = av.y;
    As[0][acol + 2][arow] = av.z;
    As[0][acol + 3][arow] = av.w;
    *(float4*)&Bs[0][brow][bcol] = wv;
    __syncthreads();

    int stage = 0;
    for (int k0 = 0; k0 < K; k0 += 8) {
        // Prefetch next tile into registers (overlaps with compute below)
        const bool has_next = (k0 + 8) < K;
        if (has_next) {
            av = *(const float4*)(Ap + k0 + 8);
            wv = *(const float4*)(Wp + (size_t)(k0 + 8) * N);
        }

        #pragma unroll
        for (int k = 0; k < 8; k++) {
            float a0[8], b0[8];
            *(float4*)&a0[0] = *(const float4*)&As[stage][k][ty * 8];
            *(float4*)&a0[4] = *(const float4*)&As[stage][k][ty * 8 + 4];
            *(float4*)&b0[0] = *(const float4*)&Bs[stage][k][tx * 8];
            *(float4*)&b0[4] = *(const float4*)&Bs[stage][k][tx * 8 + 4];
            #pragma unroll
            for (int i = 0; i < 8; i++)
                #pragma unroll
                for (int j = 0; j < 8; j++)
                    acc[i][j] = fmaf(a0[i], b0[j], acc[i][j]);
        }

        if (has_next) {
            const int ns = stage ^ 1;
            As[ns][acol + 0][arow] = av.x;
            As[ns][acol + 1][arow] = av.y;
            As[ns][acol + 2][arow] = av.z;
            As[ns][acol + 3][arow] = av.w;
            *(float4*)&Bs[ns][brow][bcol] = wv;
            __syncthreads();
            stage = ns;
        }
    }

    float* Cp = C + (size_t)(bm + ty * 8) * N + bn + tx * 8;
    #pragma unroll
    for (int i = 0; i < 8; i++) {
        *(float4*)(Cp + (size_t)i * N)     = make_float4(acc[i][0], acc[i][1], acc[i][2], acc[i][3]);
        *(float4*)(Cp + (size_t)i * N + 4) = make_float4(acc[i][4], acc[i][5], acc[i][6], acc[i][7]);
    }
}

// Single GEMM (used for the output projection)
__global__ __launch_bounds__(256) void sgemm_kernel(
    const float* __restrict__ A, const float* __restrict__ W,
    float* __restrict__ C, int M, int N, int K)
{
    __shared__ float As[2][8][128];
    __shared__ float Bs[2][8][128];
    sgemm_body(A, W, C, M, N, K, As, Bs);
}

// Fused QKV projection: blockIdx.z in {0,1,2} selects (input, weight, output).
// Numerically identical to three separate sgemm_kernel launches.
__global__ __launch_bounds__(256) void qkv_proj_kernel(
    const float* __restrict__ Aq, const float* __restrict__ Ak, const float* __restrict__ Av,
    const float* __restrict__ Wq, const float* __restrict__ Wk, const float* __restrict__ Wv,
    float* __restrict__ Cq, float* __restrict__ Ck, float* __restrict__ Cv)
{
    __shared__ float As[2][8][128];
    __shared__ float Bs[2][8][128];
    const float* A; const float* W; float* C;
    if (blockIdx.z == 0)      { A = Aq; W = Wq; C = Cq; }
    else if (blockIdx.z == 1) { A = Ak; W = Wk; C = Ck; }
    else                      { A = Av; W = Wv; C = Cv; }
    sgemm_body(A, W, C, MROWS, DD, DD, As, Bs);
}

// ---------------------------------------------------------------------------
// Flash attention (fp32): per CTA: one (b,h) and one 128-query tile.
// BQ=128, BKV=64, 128 threads. Thread layout: rg = tid/8 (16 row groups of
// 8 query rows), cg = tid%8 (8 col groups: 8 KV cols for S, 8 d cols for O).
// Online softmax with shfl reductions over the 8 lanes of a row group.
// ---------------------------------------------------------------------------
#define BQ 128
#define BKV 64
#define SQT_LD 132   // sQt[d][q],  padded for banks + 16B alignment
#define SKT_LD 68    // sKt[d][kv]
#define SV_LD  68    // sV[kv][d]
#define SP_LD  68    // sP[q][kv]
#define FLASH_SMEM_FLOATS (64 * SQT_LD + 64 * SKT_LD + 64 * SV_LD + 128 * SP_LD)
#define FLASH_SMEM_BYTES  (FLASH_SMEM_FLOATS * 4)

__global__ __launch_bounds__(128) void flash_kernel(
    const float* __restrict__ Q, const float* __restrict__ K,
    const float* __restrict__ V, float* __restrict__ O)
{
    extern __shared__ float sm[];
    float* sQt = sm;                       // [64][SQT_LD]
    float* sKt = sQt + 64 * SQT_LD;        // [64][SKT_LD]
    float* sV  = sKt + 64 * SKT_LD;        // [64][SV_LD]
    float* sP  = sV  + 64 * SV_LD;         // [128][SP_LD]

    const int tid = threadIdx.x;
    const int qt  = blockIdx.x;            // 0..15
    const int bh  = blockIdx.y;            // 0..31
    const int b   = bh >> 4;
    const int h   = bh & 15;
    const int rg  = tid >> 3;              // 0..15
    const int cg  = tid & 7;               // 0..7

    const size_t base = (size_t)b * SS * DD + (size_t)h * DK;
    const int q0 = qt * BQ;

    // Load Q tile transposed into sQt[d][q], folding in softmax scale.
    {
        const float* Qp = Q + base + (size_t)q0 * DD;
        #pragma unroll
        for (int it = 0; it < 16; it++) {
            int idx = tid + it * 128;       // 0..2047
            int r   = idx >> 4;             // 0..127
            int c4  = (idx & 15) << 2;      // 0..60
            float4 v = *(const float4*)(Qp + (size_t)r * DD + c4);
            sQt[(c4 + 0) * SQT_LD + r] = v.x * SCALE;
            sQt[(c4 + 1) * SQT_LD + r] = v.y * SCALE;
            sQt[(c4 + 2) * SQT_LD + r] = v.z * SCALE;
            sQt[(c4 + 3) * SQT_LD + r] = v.w * SCALE;
        }
    }

    float m[8], l[8], o[8][8];
    #pragma unroll
    for (int r = 0; r < 8; r++) { m[r] = -1e30f; l[r] = 0.f; }
    #pragma unroll
    for (int r = 0; r < 8; r++)
        #pragma unroll
        for (int j = 0; j < 8; j++) o[r][j] = 0.f;

    for (int kv0 = 0; kv0 < SS; kv0 += BKV) {
        __syncthreads();   // prior PV done with sV/sP; Q stores visible (iter 0)

        // Load K tile (transposed) and V tile
        const float* Kp = K + base + (size_t)kv0 * DD;
        const float* Vp = V + base + (size_t)kv0 * DD;
        #pragma unroll
        for (int it = 0; it < 8; it++) {
            int idx = tid + it * 128;       // 0..1023
            int r   = idx >> 4;             // 0..63
            int c4  = (idx & 15) << 2;
            float4 kvv = *(const float4*)(Kp + (size_t)r * DD + c4);
            sKt[(c4 + 0) * SKT_LD + r] = kvv.x;
            sKt[(c4 + 1) * SKT_LD + r] = kvv.y;
            sKt[(c4 + 2) * SKT_LD + r] = kvv.z;
            sKt[(c4 + 3) * SKT_LD + r] = kvv.w;
            float4 vv = *(const float4*)(Vp + (size_t)r * DD + c4);
            *(float4*)&sV[r * SV_LD + c4] = vv;
        }
        __syncthreads();

        // S = Q @ K^T  (scaled already), 8x8 microtile per thread
        float s[8][8] = {};
        #pragma unroll 4
        for (int d = 0; d < 64; d++) {
            float qf[8], kf[8];
            *(float4*)&qf[0] = *(const float4*)&sQt[d * SQT_LD + rg * 8];
            *(float4*)&qf[4] = *(const float4*)&sQt[d * SQT_LD + rg * 8 + 4];
            *(float4*)&kf[0] = *(const float4*)&sKt[d * SKT_LD + cg * 8];
            *(float4*)&kf[4] = *(const float4*)&sKt[d * SKT_LD + cg * 8 + 4];
            #pragma unroll
            for (int i = 0; i < 8; i++)
                #pragma unroll
                for (int j = 0; j < 8; j++)
                    s[i][j] = fmaf(qf[i], kf[j], s[i][j]);
        }

        // Online softmax update (per query row, across 8 lanes of row group)
        #pragma unroll
        for (int r = 0; r < 8; r++) {
            float mx = s[r][0];
            #pragma unroll
            for (int j = 1; j < 8; j++) mx = fmaxf(mx, s[r][j]);
            mx = fmaxf(mx, __shfl_xor_sync(0xffffffffu, mx, 1));
            mx = fmaxf(mx, __shfl_xor_sync(0xffffffffu, mx, 2));
            mx = fmaxf(mx, __shfl_xor_sync(0xffffffffu, mx, 4));
            float mn    = fmaxf(m[r], mx);
            float alpha = __expf(m[r] - mn);
            m[r] = mn;
            float rs = 0.f;
            #pragma unroll
            for (int j = 0; j < 8; j++) {
                float p = __expf(s[r][j] - mn);
                s[r][j] = p;
                rs += p;
            }
            rs += __shfl_xor_sync(0xffffffffu, rs, 1);
            rs += __shfl_xor_sync(0xffffffffu, rs, 2);
            rs += __shfl_xor_sync(0xffffffffu, rs, 4);
            l[r] = l[r] * alpha + rs;
            #pragma unroll
            for (int j = 0; j < 8; j++) o[r][j] *= alpha;
        }

        // Stage P row-major: sP[q][kv]
        #pragma unroll
        for (int r = 0; r < 8; r++) {
            *(float4*)&sP[(rg * 8 + r) * SP_LD + cg * 8]     = make_float4(s[r][0], s[r][1], s[r][2], s[r][3]);
            *(float4*)&sP[(rg * 8 + r) * SP_LD + cg * 8 + 4] = make_float4(s[r][4], s[r][5], s[r][6], s[r][7]);
        }
        __syncthreads();

        // O += P @ V : thread owns rows rg*8..+7, cols cg*8..+7 of O
        #pragma unroll 2
        for (int k4 = 0; k4 < 16; k4++) {
            float pf[8][4];
            #pragma unroll
            for (int i = 0; i < 8; i++)
                *(float4*)&pf[i][0] = *(const float4*)&sP[(rg * 8 + i) * SP_LD + k4 * 4];
            float vf[4][8];
            #pragma unroll
            for (int kk = 0; kk < 4; kk++) {
                *(float4*)&vf[kk][0] = *(const float4*)&sV[(k4 * 4 + kk) * SV_LD + cg * 8];
                *(float4*)&vf[kk][4] = *(const float4*)&sV[(k4 * 4 + kk) * SV_LD + cg * 8 + 4];
            }
            #pragma unroll
            for (int i = 0; i < 8; i++)
                #pragma unroll
                for (int kk = 0; kk < 4; kk++)
                    #pragma unroll
                    for (int j = 0; j < 8; j++)
                        o[i][j] = fmaf(pf[i][kk], vf[kk][j], o[i][j]);
        }
    }

    // Normalize and write out: O[b, q0+row, h*64 + col]
    float* Op = O + base + (size_t)q0 * DD;
    #pragma unroll
    for (int r = 0; r < 8; r++) {
        float inv = 1.f / l[r];
        int row = rg * 8 + r;
        *(float4*)(Op + (size_t)row * DD + cg * 8) =
            make_float4(o[r][0] * inv, o[r][1] * inv, o[r][2] * inv, o[r][3] * inv);
        *(float4*)(Op + (size_t)row * DD + cg * 8 + 4) =
            make_float4(o[r][4] * inv, o[r][5] * inv, o[r][6] * inv, o[r][7] * inv);
    }
}

// ---------------------------------------------------------------------------
// Launch: fused QKV projection -> flash attention -> output projection
// ---------------------------------------------------------------------------
extern "C" void kernel_launch(void* const* d_in, const int* in_sizes, int n_in,
                              void* d_out, int out_size)
{
    const float* q  = (const float*)d_in[0];
    const float* k  = (const float*)d_in[1];
    const float* v  = (const float*)d_in[2];
    const float* Wq = (const float*)d_in[3];
    const float* Wk = (const float*)d_in[4];
    const float* Wv = (const float*)d_in[5];
    const float* Wo = (const float*)d_in[6];
    float* out = (float*)d_out;

    float *gQ, *gK, *gV, *gAO;
    cudaGetSymbolAddress((void**)&gQ,  g_Q);
    cudaGetSymbolAddress((void**)&gK,  g_K);
    cudaGetSymbolAddress((void**)&gV,  g_V);
    cudaGetSymbolAddress((void**)&gAO, g_AO);

    cudaFuncSetAttribute(flash_kernel, cudaFuncAttributeMaxDynamicSharedMemorySize,
                         FLASH_SMEM_BYTES);

    dim3 gblk(256);
    dim3 qkvgrid(DD / 128, MROWS / 128, 3);   // (8, 32, 3) — fused Q/K/V

    qkv_proj_kernel<<<qkvgrid, gblk>>>(q, k, v, Wq, Wk, Wv, gQ, gK, gV);

    dim3 fgrid(SS / BQ, BB * HH);             // (16, 32)
    flash_kernel<<<fgrid, 128, FLASH_SMEM_BYTES>>>(gQ, gK, gV, gAO);

    dim3 ggrid(DD / 128, MROWS / 128);        // (8, 32)
    sgemm_kernel<<<ggrid, gblk>>>(gAO, Wo, out, MROWS, DD, DD);
}

// round 17
// speedup vs baseline: 1.3767x; 1.3767x over previous
#include <cuda_runtime.h>
#include <cuda_bf16.h>
#include <math.h>
#include <stdint.h>

// Problem constants
#define BB   2
#define SS   2048
#define DD   1024
#define HH   16
#define DK   64
#define MROWS (BB * SS)      // 4096
#define SCALE 0.125f         // 1/sqrt(64)

// ---------------------------------------------------------------------------
// Scratch (allocation-free rule: __device__ globals)
// ---------------------------------------------------------------------------
__device__ float g_Q[MROWS * DD];
__device__ float g_K[MROWS * DD];
__device__ float g_V[MROWS * DD];
__device__ float g_AO[MROWS * DD];

__device__ __forceinline__ uint32_t smem_u32(const void* p) {
    uint32_t a;
    asm("{ .reg .u64 t; cvta.to.shared.u64 t, %1; cvt.u32.u64 %0, t; }"
        : "=r"(a) : "l"(p));
    return a;
}

__device__ __forceinline__ uint32_t packbf(__nv_bfloat16 e0, __nv_bfloat16 e1) {
    uint16_t l = *(uint16_t*)&e0, h = *(uint16_t*)&e1;
    return (uint32_t)l | ((uint32_t)h << 16);
}

#define LDMX4(r, addr) \
    asm volatile("ldmatrix.sync.aligned.m8n8.x4.shared.b16 {%0,%1,%2,%3}, [%4];" \
        : "=r"((r)[0]), "=r"((r)[1]), "=r"((r)[2]), "=r"((r)[3]) : "r"(addr))

#define LDMX2T(r, addr) \
    asm volatile("ldmatrix.sync.aligned.m8n8.x2.trans.shared.b16 {%0,%1}, [%2];" \
        : "=r"((r)[0]), "=r"((r)[1]) : "r"(addr))

#define MMA_BF16(c, a, b) \
    asm volatile("mma.sync.aligned.m16n8k16.row.col.f32.bf16.bf16.f32 " \
        "{%0,%1,%2,%3}, {%4,%5,%6,%7}, {%8,%9}, {%0,%1,%2,%3};" \
        : "+f"((c)[0]), "+f"((c)[1]), "+f"((c)[2]), "+f"((c)[3]) \
        : "r"((a)[0]), "r"((a)[1]), "r"((a)[2]), "r"((a)[3]), "r"((b)[0]), "r"((b)[1]))

// ---------------------------------------------------------------------------
// Tensor-core GEMM via mma.sync (compute_103-legal), bf16x3 split for
// fp32-level precision: C += Ah*Bh + Ah*Bl + Al*Bh, fp32 accum.
// C[M,N] = A[M,K] @ W[K,N]; M=4096, N=K=1024. 128x128 tile, BK=32, 8 warps
// (4x2), warp tile 32x64 = 2x8 m16n8k16. A smem [m][k] pad40; W smem [k][n]
// pad136 (native layout, B frags via ldmatrix.x2.trans). Double-buffered.
// blockIdx.z selects one of 3 (A, W, C) triples (fused QKV).
// ---------------------------------------------------------------------------
#define MG_BK    32
#define A_LD     40                    // bf16 per A row (32 + 8 pad)
#define B_LD     136                   // bf16 per B row (128 + 8 pad)
#define A_TILE_B (128 * A_LD * 2)      // 10240 bytes per copy
#define B_TILE_B (MG_BK * B_LD * 2)    // 8704 bytes per copy
#define OFF_AH   0
#define OFF_AL   (A_TILE_B)
#define OFF_BH   (2 * A_TILE_B)
#define OFF_BL   (2 * A_TILE_B + B_TILE_B)
#define STAGE_B  (2 * A_TILE_B + 2 * B_TILE_B)  // 37888
#define MG_SMEM  (2 * STAGE_B)                  // 75776

__global__ __launch_bounds__(256, 2) void mma_gemm(
    const float* __restrict__ A0, const float* __restrict__ W0, float* __restrict__ C0,
    const float* __restrict__ A1, const float* __restrict__ W1, float* __restrict__ C1,
    const float* __restrict__ A2, const float* __restrict__ W2, float* __restrict__ C2)
{
    extern __shared__ char smc[];
    const float* A; const float* W; float* C;
    if (blockIdx.z == 0)      { A = A0; W = W0; C = C0; }
    else if (blockIdx.z == 1) { A = A1; W = W1; C = C1; }
    else                      { A = A2; W = W2; C = C2; }

    const int tid  = threadIdx.x;
    const int wid  = tid >> 5;
    const int lane = tid & 31;
    const int bm   = blockIdx.y * 128;
    const int bn   = blockIdx.x * 128;
    const int wm   = (wid >> 1) * 32;      // warp row offset (0,32,64,96)
    const int wn   = (wid & 1) * 64;       // warp col offset (0,64)
    const uint32_t sb = smem_u32(smc);

    float acc[2][8][4];
    #pragma unroll
    for (int mi = 0; mi < 2; mi++)
        #pragma unroll
        for (int ni = 0; ni < 8; ni++)
            #pragma unroll
            for (int j = 0; j < 4; j++) acc[mi][ni][j] = 0.f;

    for (int k0 = 0; k0 < DD; k0 += MG_BK) {
        const int s = (k0 >> 5) & 1;
        char* st = smc + s * STAGE_B;

        __syncthreads();   // prior compute on this stage finished

        // Load + convert A chunk: 128 x 32 fp32 -> bf16 hi/lo at [m][k] pad A_LD
        {
            const int c4 = tid & 7;        // float4 col 0..7
            const int r0 = tid >> 3;       // 0..31
            #pragma unroll
            for (int it = 0; it < 4; it++) {
                int r = r0 + it * 32;
                float4 a = *(const float4*)(A + (size_t)(bm + r) * DD + k0 + c4 * 4);
                __nv_bfloat16 h0 = __float2bfloat16_rn(a.x);
                __nv_bfloat16 h1 = __float2bfloat16_rn(a.y);
                __nv_bfloat16 h2 = __float2bfloat16_rn(a.z);
                __nv_bfloat16 h3 = __float2bfloat16_rn(a.w);
                __nv_bfloat16 l0 = __float2bfloat16_rn(a.x - __bfloat162float(h0));
                __nv_bfloat16 l1 = __float2bfloat16_rn(a.y - __bfloat162float(h1));
                __nv_bfloat16 l2 = __float2bfloat16_rn(a.z - __bfloat162float(h2));
                __nv_bfloat16 l3 = __float2bfloat16_rn(a.w - __bfloat162float(h3));
                uint32_t off = (uint32_t)(r * A_LD + c4 * 4) * 2;
                *(uint2*)(st + OFF_AH + off) = make_uint2(packbf(h0, h1), packbf(h2, h3));
                *(uint2*)(st + OFF_AL + off) = make_uint2(packbf(l0, l1), packbf(l2, l3));
            }
        }
        // Load + convert W chunk: 32 x 128 fp32 -> bf16 hi/lo at [k][n] pad B_LD
        {
            const int c4 = tid & 31;       // float4 col 0..31
            const int r0 = tid >> 5;       // 0..7
            #pragma unroll
            for (int it = 0; it < 4; it++) {
                int r = r0 + it * 8;
                float4 w = *(const float4*)(W + (size_t)(k0 + r) * DD + bn + c4 * 4);
                __nv_bfloat16 h0 = __float2bfloat16_rn(w.x);
                __nv_bfloat16 h1 = __float2bfloat16_rn(w.y);
                __nv_bfloat16 h2 = __float2bfloat16_rn(w.z);
                __nv_bfloat16 h3 = __float2bfloat16_rn(w.w);
                __nv_bfloat16 l0 = __float2bfloat16_rn(w.x - __bfloat162float(h0));
                __nv_bfloat16 l1 = __float2bfloat16_rn(w.y - __bfloat162float(h1));
                __nv_bfloat16 l2 = __float2bfloat16_rn(w.z - __bfloat162float(h2));
                __nv_bfloat16 l3 = __float2bfloat16_rn(w.w - __bfloat162float(h3));
                uint32_t off = (uint32_t)(r * B_LD + c4 * 4) * 2;
                *(uint2*)(st + OFF_BH + off) = make_uint2(packbf(h0, h1), packbf(h2, h3));
                *(uint2*)(st + OFF_BL + off) = make_uint2(packbf(l0, l1), packbf(l2, l3));
            }
        }
        __syncthreads();

        const uint32_t aBH = sb + s * STAGE_B + OFF_AH;
        const uint32_t aBL = sb + s * STAGE_B + OFF_AL;
        const uint32_t bBH = sb + s * STAGE_B + OFF_BH;
        const uint32_t bBL = sb + s * STAGE_B + OFF_BL;

        #pragma unroll
        for (int k16 = 0; k16 < 2; k16++) {
            const int kk = k16 * 16;
            uint32_t ah[2][4], al[2][4];
            #pragma unroll
            for (int mi = 0; mi < 2; mi++) {
                int row = wm + mi * 16 + (lane & 15);
                int col = kk + (lane >> 4) * 8;
                uint32_t off = (uint32_t)(row * A_LD + col) * 2;
                LDMX4(ah[mi], aBH + off);
                LDMX4(al[mi], aBL + off);
            }
            #pragma unroll
            for (int ni = 0; ni < 8; ni++) {
                int brow = kk + (lane & 15);
                int bcol = wn + ni * 8;
                uint32_t off = (uint32_t)(brow * B_LD + bcol) * 2;
                uint32_t bh[2], bl[2];
                LDMX2T(bh, bBH + off);
                LDMX2T(bl, bBL + off);
                #pragma unroll
                for (int mi = 0; mi < 2; mi++) {
                    MMA_BF16(acc[mi][ni], ah[mi], bh);
                    MMA_BF16(acc[mi][ni], ah[mi], bl);
                    MMA_BF16(acc[mi][ni], al[mi], bh);
                }
            }
        }
    }

    // Epilogue: c0,c1 -> (row=gr, col=2*tig), c2,c3 -> (row=gr+8)
    const int gr  = lane >> 2;
    const int tig = lane & 3;
    #pragma unroll
    for (int mi = 0; mi < 2; mi++) {
        #pragma unroll
        for (int ni = 0; ni < 8; ni++) {
            int row = bm + wm + mi * 16 + gr;
            int col = bn + wn + ni * 8 + tig * 2;
            *(float2*)(C + (size_t)row * DD + col) =
                make_float2(acc[mi][ni][0], acc[mi][ni][1]);
            *(float2*)(C + (size_t)(row + 8) * DD + col) =
                make_float2(acc[mi][ni][2], acc[mi][ni][3]);
        }
    }
}

// ---------------------------------------------------------------------------
// Flash attention (fp32), unchanged from the passing baseline.
// ---------------------------------------------------------------------------
#define BQ 128
#define BKV 64
#define SQT_LD 132
#define SKT_LD 68
#define SV_LD  68
#define SP_LD  68
#define FLASH_SMEM_FLOATS (64 * SQT_LD + 64 * SKT_LD + 64 * SV_LD + 128 * SP_LD)
#define FLASH_SMEM_BYTES  (FLASH_SMEM_FLOATS * 4)

__global__ __launch_bounds__(128) void flash_kernel(
    const float* __restrict__ Q, const float* __restrict__ K,
    const float* __restrict__ V, float* __restrict__ O)
{
    extern __shared__ float sm[];
    float* sQt = sm;
    float* sKt = sQt + 64 * SQT_LD;
    float* sV  = sKt + 64 * SKT_LD;
    float* sP  = sV  + 64 * SV_LD;

    const int tid = threadIdx.x;
    const int qt  = blockIdx.x;
    const int bh  = blockIdx.y;
    const int b   = bh >> 4;
    const int h   = bh & 15;
    const int rg  = tid >> 3;
    const int cg  = tid & 7;

    const size_t base = (size_t)b * SS * DD + (size_t)h * DK;
    const int q0 = qt * BQ;

    {
        const float* Qp = Q + base + (size_t)q0 * DD;
        #pragma unroll
        for (int it = 0; it < 16; it++) {
            int idx = tid + it * 128;
            int r   = idx >> 4;
            int c4  = (idx & 15) << 2;
            float4 v = *(const float4*)(Qp + (size_t)r * DD + c4);
            sQt[(c4 + 0) * SQT_LD + r] = v.x * SCALE;
            sQt[(c4 + 1) * SQT_LD + r] = v.y * SCALE;
            sQt[(c4 + 2) * SQT_LD + r] = v.z * SCALE;
            sQt[(c4 + 3) * SQT_LD + r] = v.w * SCALE;
        }
    }

    float m[8], l[8], o[8][8];
    #pragma unroll
    for (int r = 0; r < 8; r++) { m[r] = -1e30f; l[r] = 0.f; }
    #pragma unroll
    for (int r = 0; r < 8; r++)
        #pragma unroll
        for (int j = 0; j < 8; j++) o[r][j] = 0.f;

    for (int kv0 = 0; kv0 < SS; kv0 += BKV) {
        __syncthreads();

        const float* Kp = K + base + (size_t)kv0 * DD;
        const float* Vp = V + base + (size_t)kv0 * DD;
        #pragma unroll
        for (int it = 0; it < 8; it++) {
            int idx = tid + it * 128;
            int r   = idx >> 4;
            int c4  = (idx & 15) << 2;
            float4 kvv = *(const float4*)(Kp + (size_t)r * DD + c4);
            sKt[(c4 + 0) * SKT_LD + r] = kvv.x;
            sKt[(c4 + 1) * SKT_LD + r] = kvv.y;
            sKt[(c4 + 2) * SKT_LD + r] = kvv.z;
            sKt[(c4 + 3) * SKT_LD + r] = kvv.w;
            float4 vv = *(const float4*)(Vp + (size_t)r * DD + c4);
            *(float4*)&sV[r * SV_LD + c4] = vv;
        }
        __syncthreads();

        float s[8][8] = {};
        #pragma unroll 4
        for (int d = 0; d < 64; d++) {
            float qf[8], kf[8];
            *(float4*)&qf[0] = *(const float4*)&sQt[d * SQT_LD + rg * 8];
            *(float4*)&qf[4] = *(const float4*)&sQt[d * SQT_LD + rg * 8 + 4];
            *(float4*)&kf[0] = *(const float4*)&sKt[d * SKT_LD + cg * 8];
            *(float4*)&kf[4] = *(const float4*)&sKt[d * SKT_LD + cg * 8 + 4];
            #pragma unroll
            for (int i = 0; i < 8; i++)
                #pragma unroll
                for (int j = 0; j < 8; j++)
                    s[i][j] = fmaf(qf[i], kf[j], s[i][j]);
        }

        #pragma unroll
        for (int r = 0; r < 8; r++) {
            float mx = s[r][0];
            #pragma unroll
            for (int j = 1; j < 8; j++) mx = fmaxf(mx, s[r][j]);
            mx = fmaxf(mx, __shfl_xor_sync(0xffffffffu, mx, 1));
            mx = fmaxf(mx, __shfl_xor_sync(0xffffffffu, mx, 2));
            mx = fmaxf(mx, __shfl_xor_sync(0xffffffffu, mx, 4));
            float mn    = fmaxf(m[r], mx);
            float alpha = __expf(m[r] - mn);
            m[r] = mn;
            float rs = 0.f;
            #pragma unroll
            for (int j = 0; j < 8; j++) {
                float p = __expf(s[r][j] - mn);
                s[r][j] = p;
                rs += p;
            }
            rs += __shfl_xor_sync(0xffffffffu, rs, 1);
            rs += __shfl_xor_sync(0xffffffffu, rs, 2);
            rs += __shfl_xor_sync(0xffffffffu, rs, 4);
            l[r] = l[r] * alpha + rs;
            #pragma unroll
            for (int j = 0; j < 8; j++) o[r][j] *= alpha;
        }

        #pragma unroll
        for (int r = 0; r < 8; r++) {
            *(float4*)&sP[(rg * 8 + r) * SP_LD + cg * 8]     = make_float4(s[r][0], s[r][1], s[r][2], s[r][3]);
            *(float4*)&sP[(rg * 8 + r) * SP_LD + cg * 8 + 4] = make_float4(s[r][4], s[r][5], s[r][6], s[r][7]);
        }
        __syncthreads();

        #pragma unroll 2
        for (int k4 = 0; k4 < 16; k4++) {
            float pf[8][4];
            #pragma unroll
            for (int i = 0; i < 8; i++)
                *(float4*)&pf[i][0] = *(const float4*)&sP[(rg * 8 + i) * SP_LD + k4 * 4];
            float vf[4][8];
            #pragma unroll
            for (int kk = 0; kk < 4; kk++) {
                *(float4*)&vf[kk][0] = *(const float4*)&sV[(k4 * 4 + kk) * SV_LD + cg * 8];
                *(float4*)&vf[kk][4] = *(const float4*)&sV[(k4 * 4 + kk) * SV_LD + cg * 8 + 4];
            }
            #pragma unroll
            for (int i = 0; i < 8; i++)
                #pragma unroll
                for (int kk = 0; kk < 4; kk++)
                    #pragma unroll
                    for (int j = 0; j < 8; j++)
                        o[i][j] = fmaf(pf[i][kk], vf[kk][j], o[i][j]);
        }
    }

    float* Op = O + base + (size_t)q0 * DD;
    #pragma unroll
    for (int r = 0; r < 8; r++) {
        float inv = 1.f / l[r];
        int row = rg * 8 + r;
        *(float4*)(Op + (size_t)row * DD + cg * 8) =
            make_float4(o[r][0] * inv, o[r][1] * inv, o[r][2] * inv, o[r][3] * inv);
        *(float4*)(Op + (size_t)row * DD + cg * 8 + 4) =
            make_float4(o[r][4] * inv, o[r][5] * inv, o[r][6] * inv, o[r][7] * inv);
    }
}

// ---------------------------------------------------------------------------
// Launch: mma.sync fused QKV -> fp32 flash attention -> mma.sync Wo projection
// ---------------------------------------------------------------------------
extern "C" void kernel_launch(void* const* d_in, const int* in_sizes, int n_in,
                              void* d_out, int out_size)
{
    const float* q  = (const float*)d_in[0];
    const float* k  = (const float*)d_in[1];
    const float* v  = (const float*)d_in[2];
    const float* Wq = (const float*)d_in[3];
    const float* Wk = (const float*)d_in[4];
    const float* Wv = (const float*)d_in[5];
    const float* Wo = (const float*)d_in[6];
    float* out = (float*)d_out;

    float *gQ, *gK, *gV, *gAO;
    cudaGetSymbolAddress((void**)&gQ,  g_Q);
    cudaGetSymbolAddress((void**)&gK,  g_K);
    cudaGetSymbolAddress((void**)&gV,  g_V);
    cudaGetSymbolAddress((void**)&gAO, g_AO);

    cudaFuncSetAttribute(mma_gemm, cudaFuncAttributeMaxDynamicSharedMemorySize, MG_SMEM);
    cudaFuncSetAttribute(flash_kernel, cudaFuncAttributeMaxDynamicSharedMemorySize,
                         FLASH_SMEM_BYTES);

    dim3 qkvgrid(DD / 128, MROWS / 128, 3);   // (8, 32, 3)
    mma_gemm<<<qkvgrid, 256, MG_SMEM>>>(q, Wq, gQ, k, Wk, gK, v, Wv, gV);

    dim3 fgrid(SS / BQ, BB * HH);             // (16, 32)
    flash_kernel<<<fgrid, 128, FLASH_SMEM_BYTES>>>(gQ, gK, gV, gAO);

    dim3 ogrid(DD / 128, MROWS / 128, 1);     // (8, 32, 1)
    mma_gemm<<<ogrid, 256, MG_SMEM>>>(gAO, Wo, out, gAO, Wo, out, gAO, Wo, out);
}